// round 6
// baseline (speedup 1.0000x reference)
#include <cuda_runtime.h>

#define N_NODES 100000
#define N_EDGES 3200000
#define IN_F 256
#define OUT_F 64

// ---- scratch (device globals; no runtime allocation) ----
__device__ __align__(16) int   g_deg[N_NODES];
__device__ __align__(16) float g_norm[N_NODES];
__device__ __align__(16) float g_w[N_EDGES];
__device__ __align__(16) float g_y0[(size_t)N_NODES * OUT_F];
__device__ __align__(16) float g_y1[(size_t)N_NODES * OUT_F];

// ---------------------------------------------------------
__global__ void k_deg_zero() {
    int i = blockIdx.x * blockDim.x + threadIdx.x;
    if (i < N_NODES) g_deg[i] = 0;
}

__global__ void k_deg(const int* __restrict__ dst) {
    int i = blockIdx.x * blockDim.x + threadIdx.x;
    if (i < N_EDGES) atomicAdd(&g_deg[dst[i]], 1);
}

__global__ void k_norm() {
    int i = blockIdx.x * blockDim.x + threadIdx.x;
    if (i < N_NODES) {
        int d = g_deg[i];
        float df = (float)(d < 1 ? 1 : d);
        g_norm[i] = rsqrtf(df);
    }
}

__global__ void k_edgew(const int* __restrict__ src, const int* __restrict__ dst) {
    int i = blockIdx.x * blockDim.x + threadIdx.x;
    if (i < N_EDGES) g_w[i] = g_norm[src[i]] * g_norm[dst[i]];
}

// ---- GEMM: y0[N,64] = x[N,256] @ W[256,64] --------------
// block = 256 threads, tile = 64 nodes x 64 cols, k-chunks of 32.
// thread (tx = tid&15, ty = tid>>4) computes 4 nodes x 4 cols.
__global__ void k_gemm(const float* __restrict__ x, const float* __restrict__ W) {
    __shared__ float xs[32][64];   // [k][node] (transposed for float4 node reads)
    __shared__ float sW[32][64];   // [k][col]

    const int tid = threadIdx.x;
    const int tx = tid & 15;
    const int ty = tid >> 4;
    const int node0 = blockIdx.x * 64;

    float acc[4][4];
#pragma unroll
    for (int i = 0; i < 4; i++)
#pragma unroll
        for (int j = 0; j < 4; j++) acc[i][j] = 0.f;

    for (int kc = 0; kc < IN_F; kc += 32) {
        // load x chunk (coalesced: 32 consecutive k per warp-row)
#pragma unroll
        for (int r = 0; r < 8; r++) {
            int n = r * 8 + (tid >> 5);   // 0..63
            int k = tid & 31;
            int gn = node0 + n;
            float v = 0.f;
            if (gn < N_NODES) v = x[(size_t)gn * IN_F + kc + k];
            xs[k][n] = v;
        }
        // load W chunk (fully coalesced)
#pragma unroll
        for (int r = 0; r < 8; r++) {
            int idx = r * 256 + tid;      // 0..2047
            sW[idx >> 6][idx & 63] = W[(size_t)(kc + (idx >> 6)) * OUT_F + (idx & 63)];
        }
        __syncthreads();

#pragma unroll
        for (int k = 0; k < 32; k++) {
            float4 a  = *(const float4*)&xs[k][ty * 4];
            float4 wv = *(const float4*)&sW[k][tx * 4];
            acc[0][0] += a.x * wv.x; acc[0][1] += a.x * wv.y; acc[0][2] += a.x * wv.z; acc[0][3] += a.x * wv.w;
            acc[1][0] += a.y * wv.x; acc[1][1] += a.y * wv.y; acc[1][2] += a.y * wv.z; acc[1][3] += a.y * wv.w;
            acc[2][0] += a.z * wv.x; acc[2][1] += a.z * wv.y; acc[2][2] += a.z * wv.z; acc[2][3] += a.z * wv.w;
            acc[3][0] += a.w * wv.x; acc[3][1] += a.w * wv.y; acc[3][2] += a.w * wv.z; acc[3][3] += a.w * wv.w;
        }
        __syncthreads();
    }

#pragma unroll
    for (int i = 0; i < 4; i++) {
        int n = node0 + ty * 4 + i;
        if (n < N_NODES) {
            float4 o = make_float4(acc[i][0], acc[i][1], acc[i][2], acc[i][3]);
            *(float4*)&g_y0[(size_t)n * OUT_F + tx * 4] = o;
        }
    }
}

// ---- zero / bias-init helpers ---------------------------
__global__ void k_zero_y1() {
    int i = blockIdx.x * blockDim.x + threadIdx.x;  // float4 index
    const int n4 = N_NODES * OUT_F / 4;             // 1.6M
    if (i < n4) ((float4*)g_y1)[i] = make_float4(0.f, 0.f, 0.f, 0.f);
}

__global__ void k_init_out(float* __restrict__ out, const float* __restrict__ b) {
    int i = blockIdx.x * blockDim.x + threadIdx.x;  // float4 index
    const int n4 = N_NODES * OUT_F / 4;
    if (i < n4) {
        const float4 bv = ((const float4*)b)[i & 15];   // 64 floats = 16 float4
        ((float4*)out)[i] = bv;
    }
}

// ---- one propagation hop: out[dst] += w_e * in[src] -----
// 16 threads per edge, float4 per thread, vectorized RED.
__global__ void k_prop(const float* __restrict__ in, float* __restrict__ out,
                       const int* __restrict__ src, const int* __restrict__ dst) {
    const unsigned t = blockIdx.x * blockDim.x + threadIdx.x;
    const unsigned total = (unsigned)N_EDGES * 16u;   // 51.2M
    if (t >= total) return;
    const unsigned e = t >> 4;
    const unsigned p = t & 15u;

    const int s = src[e];
    const int d = dst[e];
    const float w = g_w[e];

    const float4 v = *(const float4*)(in + (size_t)s * OUT_F + p * 4);
    float4 m = make_float4(v.x * w, v.y * w, v.z * w, v.w * w);

    float* dp = out + (size_t)d * OUT_F + p * 4;
    asm volatile("red.global.add.v4.f32 [%0], {%1,%2,%3,%4};"
                 :: "l"(dp), "f"(m.x), "f"(m.y), "f"(m.z), "f"(m.w)
                 : "memory");
}

// ---------------------------------------------------------
extern "C" void kernel_launch(void* const* d_in, const int* in_sizes, int n_in,
                              void* d_out, int out_size) {
    const float* x   = (const float*)d_in[0];
    const int*   src = (const int*)  d_in[1];
    const int*   dst = (const int*)  d_in[2];
    const float* W   = (const float*)d_in[3];
    const float* b   = (const float*)d_in[4];
    float* out = (float*)d_out;

    float* y0;  cudaGetSymbolAddress((void**)&y0, g_y0);
    float* y1;  cudaGetSymbolAddress((void**)&y1, g_y1);

    const int T = 256;
    const int gN  = (N_NODES + T - 1) / T;
    const int gE  = (N_EDGES + T - 1) / T;
    const int gF4 = (N_NODES * OUT_F / 4 + T - 1) / T;
    const int gP  = (N_EDGES * 16 + T - 1) / T;
    const int gG  = (N_NODES + 63) / 64;

    // degrees -> norms -> edge weights
    k_deg_zero<<<gN, T>>>();
    k_deg<<<gE, T>>>(dst);
    k_norm<<<gN, T>>>();
    k_edgew<<<gE, T>>>(src, dst);

    // y0 = x @ W  (project BEFORE propagating: 4x less scatter traffic)
    k_gemm<<<gG, T>>>(x, W);

    // hop 1: y1 = S y0
    k_zero_y1<<<gF4, T>>>();
    k_prop<<<gP, T>>>(y0, y1, src, dst);

    // hop 2: out = S y1 + b
    k_init_out<<<gF4, T>>>(out, b);
    k_prop<<<gP, T>>>(y1, out, src, dst);
}

// round 7
// speedup vs baseline: 1.0361x; 1.0361x over previous
#include <cuda_runtime.h>

#define N_NODES 100000
#define N_EDGES 3200000
#define IN_F 256
#define OUT_F 64

// ---- scratch (device globals; no runtime allocation) ----
__device__ __align__(16) int   g_deg[N_NODES];
__device__ __align__(16) float g_norm[N_NODES];    // deg^-1/2 (clamped)
__device__ __align__(16) float g_norm2[N_NODES];   // deg^-1  (clamped)
__device__ __align__(16) float g_y0[(size_t)N_NODES * OUT_F];  // N*(xW)
__device__ __align__(16) float g_y1[(size_t)N_NODES * OUT_F];  // hop-1 accum
__device__ __align__(16) float g_y2[(size_t)N_NODES * OUT_F];  // hop-2 accum

// ---------------------------------------------------------
__global__ void k_deg_zero() {
    int i = blockIdx.x * blockDim.x + threadIdx.x;
    if (i < N_NODES) g_deg[i] = 0;
}

__global__ void k_deg(const int* __restrict__ dst) {
    int i = blockIdx.x * blockDim.x + threadIdx.x;
    if (i < N_EDGES) atomicAdd(&g_deg[dst[i]], 1);
}

__global__ void k_norm() {
    int i = blockIdx.x * blockDim.x + threadIdx.x;
    if (i < N_NODES) {
        int d = g_deg[i];
        float df = (float)(d < 1 ? 1 : d);
        g_norm[i]  = rsqrtf(df);
        g_norm2[i] = 1.0f / df;
    }
}

// ---- zero both accumulators in one pass -----------------
__global__ void k_zero_acc() {
    int i = blockIdx.x * blockDim.x + threadIdx.x;  // float4 index
    const int n4 = N_NODES * OUT_F / 4;             // 1.6M
    if (i < n4) {
        ((float4*)g_y1)[i] = make_float4(0.f, 0.f, 0.f, 0.f);
        ((float4*)g_y2)[i] = make_float4(0.f, 0.f, 0.f, 0.f);
    }
}

// ---- GEMM: y0[N,64] = norm[n] * (x[N,256] @ W[256,64]) --
// block = 256 threads, tile = 64 nodes x 64 cols, k-chunks of 32.
// thread (tx = tid&15, ty = tid>>4) computes 4 nodes x 4 cols.
__global__ void k_gemm(const float* __restrict__ x, const float* __restrict__ W) {
    __shared__ float xs[32][64];   // [k][node]
    __shared__ float sW[32][64];   // [k][col]

    const int tid = threadIdx.x;
    const int tx = tid & 15;
    const int ty = tid >> 4;
    const int node0 = blockIdx.x * 64;

    float acc[4][4];
#pragma unroll
    for (int i = 0; i < 4; i++)
#pragma unroll
        for (int j = 0; j < 4; j++) acc[i][j] = 0.f;

    for (int kc = 0; kc < IN_F; kc += 32) {
#pragma unroll
        for (int r = 0; r < 8; r++) {
            int n = r * 8 + (tid >> 5);   // 0..63
            int k = tid & 31;
            int gn = node0 + n;
            float v = 0.f;
            if (gn < N_NODES) v = x[(size_t)gn * IN_F + kc + k];
            xs[k][n] = v;
        }
#pragma unroll
        for (int r = 0; r < 8; r++) {
            int idx = r * 256 + tid;      // 0..2047
            sW[idx >> 6][idx & 63] = W[(size_t)(kc + (idx >> 6)) * OUT_F + (idx & 63)];
        }
        __syncthreads();

#pragma unroll
        for (int k = 0; k < 32; k++) {
            float4 a  = *(const float4*)&xs[k][ty * 4];
            float4 wv = *(const float4*)&sW[k][tx * 4];
            acc[0][0] += a.x * wv.x; acc[0][1] += a.x * wv.y; acc[0][2] += a.x * wv.z; acc[0][3] += a.x * wv.w;
            acc[1][0] += a.y * wv.x; acc[1][1] += a.y * wv.y; acc[1][2] += a.y * wv.z; acc[1][3] += a.y * wv.w;
            acc[2][0] += a.z * wv.x; acc[2][1] += a.z * wv.y; acc[2][2] += a.z * wv.z; acc[2][3] += a.z * wv.w;
            acc[3][0] += a.w * wv.x; acc[3][1] += a.w * wv.y; acc[3][2] += a.w * wv.z; acc[3][3] += a.w * wv.w;
        }
        __syncthreads();
    }

#pragma unroll
    for (int i = 0; i < 4; i++) {
        int n = node0 + ty * 4 + i;
        if (n < N_NODES) {
            const float nv = g_norm[n];   // pre-scale by norm (hoisted hop-1 src weight)
            float4 o = make_float4(acc[i][0] * nv, acc[i][1] * nv,
                                   acc[i][2] * nv, acc[i][3] * nv);
            *(float4*)&g_y0[(size_t)n * OUT_F + tx * 4] = o;
        }
    }
}

// ---- propagation hop: out[dst] += (w?) * in[src] --------
// 16 threads per edge, float4 per thread, vectorized RED.
// WEIGHTED=false: hop 1 (pure sum). WEIGHTED=true: hop 2, w = norm2[src].
template <bool WEIGHTED>
__global__ void k_prop(const float* __restrict__ in, float* __restrict__ out,
                       const int* __restrict__ src, const int* __restrict__ dst) {
    const unsigned t = blockIdx.x * blockDim.x + threadIdx.x;
    const unsigned total = (unsigned)N_EDGES * 16u;   // 51.2M
    if (t >= total) return;
    const unsigned e = t >> 4;
    const unsigned p = t & 15u;

    const int s = src[e];
    const int d = dst[e];

    float4 m = *(const float4*)(in + (size_t)s * OUT_F + p * 4);
    if (WEIGHTED) {
        const float w = g_norm2[s];       // broadcast within the 16-lane group
        m.x *= w; m.y *= w; m.z *= w; m.w *= w;
    }

    float* dp = out + (size_t)d * OUT_F + p * 4;
    asm volatile("red.global.add.v4.f32 [%0], {%1,%2,%3,%4};"
                 :: "l"(dp), "f"(m.x), "f"(m.y), "f"(m.z), "f"(m.w)
                 : "memory");
}

// ---- final: out = norm * acc + b ------------------------
__global__ void k_final(float* __restrict__ out, const float* __restrict__ b) {
    int i = blockIdx.x * blockDim.x + threadIdx.x;  // float4 index
    const int n4 = N_NODES * OUT_F / 4;
    if (i < n4) {
        const int node = i >> 4;                       // 16 float4 per node
        const float nv = g_norm[node];
        const float4 a = ((const float4*)g_y2)[i];
        const float4 bv = ((const float4*)b)[i & 15];
        float4 o;
        o.x = nv * a.x + bv.x;
        o.y = nv * a.y + bv.y;
        o.z = nv * a.z + bv.z;
        o.w = nv * a.w + bv.w;
        ((float4*)out)[i] = o;
    }
}

// ---------------------------------------------------------
extern "C" void kernel_launch(void* const* d_in, const int* in_sizes, int n_in,
                              void* d_out, int out_size) {
    const float* x   = (const float*)d_in[0];
    const int*   src = (const int*)  d_in[1];
    const int*   dst = (const int*)  d_in[2];
    const float* W   = (const float*)d_in[3];
    const float* b   = (const float*)d_in[4];
    float* out = (float*)d_out;

    float* y0;  cudaGetSymbolAddress((void**)&y0, g_y0);
    float* y1;  cudaGetSymbolAddress((void**)&y1, g_y1);
    float* y2;  cudaGetSymbolAddress((void**)&y2, g_y2);

    const int T = 256;
    const int gN  = (N_NODES + T - 1) / T;
    const int gE  = (N_EDGES + T - 1) / T;
    const int gF4 = (N_NODES * OUT_F / 4 + T - 1) / T;
    const int gP  = (N_EDGES * 16 + T - 1) / T;
    const int gG  = (N_NODES + 63) / 64;

    // accumulator zeroing + degree pipeline
    k_zero_acc<<<gF4, T>>>();
    k_deg_zero<<<gN, T>>>();
    k_deg<<<gE, T>>>(dst);
    k_norm<<<gN, T>>>();

    // y0 = N * (x @ W)   (project first: 4x less edge traffic; norm folded in)
    k_gemm<<<gG, T>>>(x, W);

    // hop 1: y1 = A y0            (unweighted scatter-add)
    k_prop<false><<<gP, T>>>(y0, y1, src, dst);

    // hop 2: y2 = A (N^2 y1)      (weight folded into gather side)
    k_prop<true><<<gP, T>>>(y1, y2, src, dst);

    // out = N y2 + b
    k_final<<<gF4, T>>>(out, b);
}

// round 11
// speedup vs baseline: 1.7126x; 1.6530x over previous
#include <cuda_runtime.h>

#define N_NODES 100000
#define N_EDGES 3200000
#define IN_F 256
#define OUT_F 64

// ---- scratch (device globals; no runtime allocation) ----
__device__ __align__(16) int   g_deg[N_NODES];
__device__ __align__(16) int   g_rowptr[N_NODES];
__device__ __align__(16) int   g_cursor[N_NODES];
__device__ __align__(16) int   g_csr_src[N_EDGES];
__device__ int   g_alloc;
__device__ __align__(16) float g_norm[N_NODES];    // deg^-1/2 (clamped)
__device__ __align__(16) float g_norm2[N_NODES];   // deg^-1   (clamped)
__device__ __align__(16) float g_y0[(size_t)N_NODES * OUT_F];  // N*(xW)
__device__ __align__(16) float g_y1[(size_t)N_NODES * OUT_F];  // hop-1 result

// ---------------------------------------------------------
__global__ void k_deg_zero() {
    int i = blockIdx.x * blockDim.x + threadIdx.x;
    if (i < N_NODES) g_deg[i] = 0;
    if (i == 0) g_alloc = 0;
}

__global__ void k_deg(const int* __restrict__ dst) {
    int i = blockIdx.x * blockDim.x + threadIdx.x;
    if (i < N_EDGES) atomicAdd(&g_deg[dst[i]], 1);
}

__global__ void k_norm() {
    int i = blockIdx.x * blockDim.x + threadIdx.x;
    if (i < N_NODES) {
        int d = g_deg[i];
        float df = (float)(d < 1 ? 1 : d);
        g_norm[i]  = rsqrtf(df);
        g_norm2[i] = 1.0f / df;
    }
}

// ---- CSR row allocation: block scan + one atomic per block ----
__global__ void k_alloc() {
    __shared__ int s[256];
    __shared__ int s_base;
    int i = blockIdx.x * blockDim.x + threadIdx.x;
    int tid = threadIdx.x;
    int d = (i < N_NODES) ? g_deg[i] : 0;

    // inclusive Hillis-Steele scan of d over the block
    s[tid] = d;
    __syncthreads();
#pragma unroll
    for (int off = 1; off < 256; off <<= 1) {
        int v = (tid >= off) ? s[tid - off] : 0;
        __syncthreads();
        s[tid] += v;
        __syncthreads();
    }
    if (tid == 255) s_base = atomicAdd(&g_alloc, s[255]);
    __syncthreads();

    if (i < N_NODES) {
        int base = s_base + s[tid] - d;   // exclusive position
        g_rowptr[i] = base;
        g_cursor[i] = base;
    }
}

// ---- scatter edges into CSR (by dst) --------------------
__global__ void k_scatter(const int* __restrict__ src, const int* __restrict__ dst) {
    int i = blockIdx.x * blockDim.x + threadIdx.x;
    if (i < N_EDGES) {
        int pos = atomicAdd(&g_cursor[dst[i]], 1);
        g_csr_src[pos] = src[i];
    }
}

// ---- GEMM: y0[N,64] = norm[n] * (x[N,256] @ W[256,64]) --
__global__ void k_gemm(const float* __restrict__ x, const float* __restrict__ W) {
    __shared__ float xs[32][64];   // [k][node]
    __shared__ float sW[32][64];   // [k][col]

    const int tid = threadIdx.x;
    const int tx = tid & 15;
    const int ty = tid >> 4;
    const int node0 = blockIdx.x * 64;

    float acc[4][4];
#pragma unroll
    for (int i = 0; i < 4; i++)
#pragma unroll
        for (int j = 0; j < 4; j++) acc[i][j] = 0.f;

    for (int kc = 0; kc < IN_F; kc += 32) {
#pragma unroll
        for (int r = 0; r < 8; r++) {
            int n = r * 8 + (tid >> 5);   // 0..63
            int k = tid & 31;
            int gn = node0 + n;
            float v = 0.f;
            if (gn < N_NODES) v = x[(size_t)gn * IN_F + kc + k];
            xs[k][n] = v;
        }
#pragma unroll
        for (int r = 0; r < 8; r++) {
            int idx = r * 256 + tid;      // 0..2047
            sW[idx >> 6][idx & 63] = W[(size_t)(kc + (idx >> 6)) * OUT_F + (idx & 63)];
        }
        __syncthreads();

#pragma unroll
        for (int k = 0; k < 32; k++) {
            float4 a  = *(const float4*)&xs[k][ty * 4];
            float4 wv = *(const float4*)&sW[k][tx * 4];
            acc[0][0] += a.x * wv.x; acc[0][1] += a.x * wv.y; acc[0][2] += a.x * wv.z; acc[0][3] += a.x * wv.w;
            acc[1][0] += a.y * wv.x; acc[1][1] += a.y * wv.y; acc[1][2] += a.y * wv.z; acc[1][3] += a.y * wv.w;
            acc[2][0] += a.z * wv.x; acc[2][1] += a.z * wv.y; acc[2][2] += a.z * wv.z; acc[2][3] += a.z * wv.w;
            acc[3][0] += a.w * wv.x; acc[3][1] += a.w * wv.y; acc[3][2] += a.w * wv.z; acc[3][3] += a.w * wv.w;
        }
        __syncthreads();
    }

#pragma unroll
    for (int i = 0; i < 4; i++) {
        int n = node0 + ty * 4 + i;
        if (n < N_NODES) {
            const float nv = g_norm[n];
            float4 o = make_float4(acc[i][0] * nv, acc[i][1] * nv,
                                   acc[i][2] * nv, acc[i][3] * nv);
            *(float4*)&g_y0[(size_t)n * OUT_F + tx * 4] = o;
        }
    }
}

// ---- pull-mode hop: 16 threads per dst node, no atomics ----
// FINAL=false (hop 1): y1[d] = norm2[d] * sum_{s in nbr(d)} y0[s]
//                      (norm2 is hop-2's src weight, pre-folded here)
// FINAL=true  (hop 2): out[d] = norm[d] * sum y1[s] + b
template <bool FINAL>
__global__ void k_gather(const float* __restrict__ in, float* __restrict__ out,
                         const float* __restrict__ b) {
    const unsigned t = blockIdx.x * blockDim.x + threadIdx.x;
    const unsigned node = t >> 4;
    const unsigned p = t & 15u;
    if (node >= N_NODES) return;

    const int beg = g_rowptr[node];
    const int end = beg + g_deg[node];

    float4 acc = make_float4(0.f, 0.f, 0.f, 0.f);
#pragma unroll 4
    for (int j = beg; j < end; j++) {
        const int s = g_csr_src[j];                       // broadcast in group
        const float4 v = *(const float4*)(in + (size_t)s * OUT_F + p * 4);
        acc.x += v.x; acc.y += v.y; acc.z += v.z; acc.w += v.w;
    }

    float4 o;
    if (FINAL) {
        const float nv = g_norm[node];
        const float4 bv = ((const float4*)b)[p];
        o.x = nv * acc.x + bv.x;
        o.y = nv * acc.y + bv.y;
        o.z = nv * acc.z + bv.z;
        o.w = nv * acc.w + bv.w;
    } else {
        const float w = g_norm2[node];
        o.x = w * acc.x; o.y = w * acc.y; o.z = w * acc.z; o.w = w * acc.w;
    }
    *(float4*)(out + (size_t)node * OUT_F + p * 4) = o;
}

// ---------------------------------------------------------
extern "C" void kernel_launch(void* const* d_in, const int* in_sizes, int n_in,
                              void* d_out, int out_size) {
    const float* x   = (const float*)d_in[0];
    const int*   src = (const int*)  d_in[1];
    const int*   dst = (const int*)  d_in[2];
    const float* W   = (const float*)d_in[3];
    const float* b   = (const float*)d_in[4];
    float* out = (float*)d_out;

    float* y0;  cudaGetSymbolAddress((void**)&y0, g_y0);
    float* y1;  cudaGetSymbolAddress((void**)&y1, g_y1);

    const int T = 256;
    const int gN = (N_NODES + T - 1) / T;
    const int gE = (N_EDGES + T - 1) / T;
    const int gG = (N_NODES + 63) / 64;
    const int gH = (N_NODES * 16 + T - 1) / T;   // 16 threads per node

    // degree histogram -> norms -> CSR (dst-sorted adjacency)
    k_deg_zero<<<gN, T>>>();
    k_deg<<<gE, T>>>(dst);
    k_norm<<<gN, T>>>();
    k_alloc<<<gN, T>>>();
    k_scatter<<<gE, T>>>(src, dst);

    // y0 = N * (x @ W)
    k_gemm<<<gG, T>>>(x, W);

    // hop 1 (pull): y1 = N^2 * (A y0)       -- no atomics
    k_gather<false><<<gH, T>>>(y0, y1, nullptr);

    // hop 2 (pull): out = N * (A y1) + b    -- no atomics
    k_gather<true><<<gH, T>>>(y1, out, b);
}

// round 12
// speedup vs baseline: 2.6341x; 1.5381x over previous
#include <cuda_runtime.h>

#define N_NODES 100000
#define N_EDGES 3200000
#define IN_F 256
#define OUT_F 64

// ---- scratch (device globals; no runtime allocation) ----
__device__ __align__(16) int   g_deg[N_NODES];
__device__ __align__(16) int   g_rowptr[N_NODES];
__device__ __align__(16) int   g_cursor[N_NODES];
__device__ __align__(16) int   g_csr_src[N_EDGES];
__device__ int   g_alloc;
__device__ __align__(16) float g_norm[N_NODES];    // deg^-1/2 (clamped)
__device__ __align__(16) float g_norm2[N_NODES];   // deg^-1   (clamped)
__device__ __align__(16) float g_y0[(size_t)N_NODES * OUT_F];  // N*(xW)
__device__ __align__(16) float g_y1[(size_t)N_NODES * OUT_F];  // hop-1 result

// ---------------------------------------------------------
__global__ void k_deg_zero() {
    int i = blockIdx.x * blockDim.x + threadIdx.x;
    if (i < N_NODES) g_deg[i] = 0;
    if (i == 0) g_alloc = 0;
}

__global__ void k_deg(const int* __restrict__ dst) {
    int i = blockIdx.x * blockDim.x + threadIdx.x;
    if (i < N_EDGES) atomicAdd(&g_deg[dst[i]], 1);
}

__global__ void k_norm() {
    int i = blockIdx.x * blockDim.x + threadIdx.x;
    if (i < N_NODES) {
        int d = g_deg[i];
        float df = (float)(d < 1 ? 1 : d);
        g_norm[i]  = rsqrtf(df);
        g_norm2[i] = 1.0f / df;
    }
}

// ---- CSR row allocation: block scan + one atomic per block ----
__global__ void k_alloc() {
    __shared__ int s[256];
    __shared__ int s_base;
    int i = blockIdx.x * blockDim.x + threadIdx.x;
    int tid = threadIdx.x;
    int d = (i < N_NODES) ? g_deg[i] : 0;

    s[tid] = d;
    __syncthreads();
#pragma unroll
    for (int off = 1; off < 256; off <<= 1) {
        int v = (tid >= off) ? s[tid - off] : 0;
        __syncthreads();
        s[tid] += v;
        __syncthreads();
    }
    if (tid == 255) s_base = atomicAdd(&g_alloc, s[255]);
    __syncthreads();

    if (i < N_NODES) {
        int base = s_base + s[tid] - d;   // exclusive position
        g_rowptr[i] = base;
        g_cursor[i] = base;
    }
}

// ---- scatter edges into CSR (by dst) --------------------
__global__ void k_scatter(const int* __restrict__ src, const int* __restrict__ dst) {
    int i = blockIdx.x * blockDim.x + threadIdx.x;
    if (i < N_EDGES) {
        int pos = atomicAdd(&g_cursor[dst[i]], 1);
        g_csr_src[pos] = src[i];
    }
}

// ---- TF32 tensor-core GEMM: y0 = norm * (x @ W) ---------
// block = 256 threads (8 warps). Tile: 128 rows x 64 cols, k-chunks of 32.
// Warp w computes rows w*16..w*16+15, all 64 cols via 8 m16n8k8 tiles.
__device__ __forceinline__ unsigned f2tf32(float f) {
    unsigned r;
    asm("cvt.rna.tf32.f32 %0, %1;" : "=r"(r) : "f"(f));
    return r;
}

__global__ void k_gemm(const float* __restrict__ x, const float* __restrict__ W) {
    __shared__ float xs[128][36];   // 128 rows x 32 k (pad 36: conflict-free, 16B-aligned)
    __shared__ float sW[32][68];    // 32 k x 64 cols (pad 68)

    const int tid  = threadIdx.x;
    const int wid  = tid >> 5;
    const int lane = tid & 31;
    const int node0 = blockIdx.x * 128;

    const int gid = lane >> 2;      // 0..7  (row group)
    const int qid = lane & 3;       // 0..3  (k/col quad)

    float c[8][4];                  // 8 n-tiles x 4 accum regs
#pragma unroll
    for (int nt = 0; nt < 8; nt++)
#pragma unroll
        for (int i = 0; i < 4; i++) c[nt][i] = 0.f;

    for (int kc = 0; kc < IN_F; kc += 32) {
        // load x tile: 128x32 = 1024 float4, 4 per thread
#pragma unroll
        for (int r = 0; r < 4; r++) {
            int idx4 = r * 256 + tid;          // 0..1023
            int row  = idx4 >> 3;              // 0..127
            int col4 = idx4 & 7;               // 0..7
            int gn = node0 + row;
            float4 v = make_float4(0.f, 0.f, 0.f, 0.f);
            if (gn < N_NODES)
                v = *(const float4*)&x[(size_t)gn * IN_F + kc + col4 * 4];
            *(float4*)&xs[row][col4 * 4] = v;
        }
        // load W tile: 32x64 = 512 float4, 2 per thread
#pragma unroll
        for (int r = 0; r < 2; r++) {
            int idx4 = r * 256 + tid;          // 0..511
            int row  = idx4 >> 4;              // 0..31
            int col4 = idx4 & 15;              // 0..15
            float4 v = *(const float4*)&W[(size_t)(kc + row) * OUT_F + col4 * 4];
            *(float4*)&sW[row][col4 * 4] = v;
        }
        __syncthreads();

#pragma unroll
        for (int kk = 0; kk < 4; kk++) {       // 4 k-steps of 8
            const int k0 = kk * 8;
            const int r0 = wid * 16 + gid;
            // A fragment (m16k8, row-major)
            unsigned a0 = f2tf32(xs[r0    ][k0 + qid    ]);
            unsigned a1 = f2tf32(xs[r0 + 8][k0 + qid    ]);
            unsigned a2 = f2tf32(xs[r0    ][k0 + qid + 4]);
            unsigned a3 = f2tf32(xs[r0 + 8][k0 + qid + 4]);
#pragma unroll
            for (int nt = 0; nt < 8; nt++) {
                // B fragment (k8n8, col-major view of row-major sW)
                unsigned b0 = f2tf32(sW[k0 + qid    ][nt * 8 + gid]);
                unsigned b1 = f2tf32(sW[k0 + qid + 4][nt * 8 + gid]);
                asm volatile(
                    "mma.sync.aligned.m16n8k8.row.col.f32.tf32.tf32.f32 "
                    "{%0,%1,%2,%3}, {%4,%5,%6,%7}, {%8,%9}, {%0,%1,%2,%3};"
                    : "+f"(c[nt][0]), "+f"(c[nt][1]), "+f"(c[nt][2]), "+f"(c[nt][3])
                    : "r"(a0), "r"(a1), "r"(a2), "r"(a3), "r"(b0), "r"(b1));
            }
        }
        __syncthreads();
    }

    // epilogue: scale by norm, write two rows per thread
    {
        const int r_lo = node0 + wid * 16 + gid;
        const int r_hi = r_lo + 8;
        if (r_lo < N_NODES) {
            const float nv = g_norm[r_lo];
#pragma unroll
            for (int nt = 0; nt < 8; nt++) {
                float2 o = make_float2(c[nt][0] * nv, c[nt][1] * nv);
                *(float2*)&g_y0[(size_t)r_lo * OUT_F + nt * 8 + qid * 2] = o;
            }
        }
        if (r_hi < N_NODES) {
            const float nv = g_norm[r_hi];
#pragma unroll
            for (int nt = 0; nt < 8; nt++) {
                float2 o = make_float2(c[nt][2] * nv, c[nt][3] * nv);
                *(float2*)&g_y0[(size_t)r_hi * OUT_F + nt * 8 + qid * 2] = o;
            }
        }
    }
}

// ---- pull-mode hop: 16 threads per dst node, no atomics ----
// FINAL=false (hop 1): y1[d] = norm2[d] * sum_{s in nbr(d)} y0[s]
// FINAL=true  (hop 2): out[d] = norm[d] * sum y1[s] + b
template <bool FINAL>
__global__ void k_gather(const float* __restrict__ in, float* __restrict__ out,
                         const float* __restrict__ b) {
    const unsigned t = blockIdx.x * blockDim.x + threadIdx.x;
    const unsigned node = t >> 4;
    const unsigned p = t & 15u;
    if (node >= N_NODES) return;

    const int beg = g_rowptr[node];
    const int end = beg + g_deg[node];

    float4 acc = make_float4(0.f, 0.f, 0.f, 0.f);
#pragma unroll 4
    for (int j = beg; j < end; j++) {
        const int s = g_csr_src[j];                       // broadcast in group
        const float4 v = *(const float4*)(in + (size_t)s * OUT_F + p * 4);
        acc.x += v.x; acc.y += v.y; acc.z += v.z; acc.w += v.w;
    }

    float4 o;
    if (FINAL) {
        const float nv = g_norm[node];
        const float4 bv = ((const float4*)b)[p];
        o.x = nv * acc.x + bv.x;
        o.y = nv * acc.y + bv.y;
        o.z = nv * acc.z + bv.z;
        o.w = nv * acc.w + bv.w;
    } else {
        const float w = g_norm2[node];
        o.x = w * acc.x; o.y = w * acc.y; o.z = w * acc.z; o.w = w * acc.w;
    }
    *(float4*)(out + (size_t)node * OUT_F + p * 4) = o;
}

// ---------------------------------------------------------
extern "C" void kernel_launch(void* const* d_in, const int* in_sizes, int n_in,
                              void* d_out, int out_size) {
    const float* x   = (const float*)d_in[0];
    const int*   src = (const int*)  d_in[1];
    const int*   dst = (const int*)  d_in[2];
    const float* W   = (const float*)d_in[3];
    const float* b   = (const float*)d_in[4];
    float* out = (float*)d_out;

    float* y0;  cudaGetSymbolAddress((void**)&y0, g_y0);
    float* y1;  cudaGetSymbolAddress((void**)&y1, g_y1);

    const int T = 256;
    const int gN = (N_NODES + T - 1) / T;
    const int gE = (N_EDGES + T - 1) / T;
    const int gG = (N_NODES + 127) / 128;
    const int gH = (N_NODES * 16 + T - 1) / T;   // 16 threads per node

    // degree histogram -> norms -> CSR (dst-sorted adjacency)
    k_deg_zero<<<gN, T>>>();
    k_deg<<<gE, T>>>(dst);
    k_norm<<<gN, T>>>();
    k_alloc<<<gN, T>>>();
    k_scatter<<<gE, T>>>(src, dst);

    // y0 = N * (x @ W)   (tf32 tensor cores)
    k_gemm<<<gG, T>>>(x, W);

    // hop 1 (pull): y1 = N^2 * (A y0)       -- no atomics
    k_gather<false><<<gH, T>>>(y0, y1, nullptr);

    // hop 2 (pull): out = N * (A y1) + b    -- no atomics
    k_gather<true><<<gH, T>>>(y1, out, b);
}